// round 13
// baseline (speedup 1.0000x reference)
#include <cuda_runtime.h>
#include <math.h>

// Problem constants
#define NQ   64          // queries
#define DD   256         // feature dim
#define NS   4096        // bank size
#define IMG  65536       // C*H*W floats per image
#define FPB  32          // features per sim block
#define QPB  32          // queries per sim block
#define FBLOCKS (NS / FPB)     // 128 f-tiles
#define SIMBLOCKS (2 * FBLOCKS) // 256 blocks (2 q-halves)

// smem layout for sim kernel (transposed, padded strides)
#define TS_STRIDE 36     // 32 rows + 4 pad (float2/float4-aligned, conflict-free)
#define TS_FLOATS (DD * TS_STRIDE)   // 9216 floats per tile
#define SMEM_BYTES (2 * TS_FLOATS * 4 + QPB * 16 * 8)  // 77824 B -> 2 blocks/SM

// Per-(query, f-tile) partial argmax results. Every slot is rewritten on
// every replay -> no reset kernel, no atomics, fully deterministic.
__device__ unsigned long long g_part[NQ * FBLOCKS];

__device__ __forceinline__ unsigned long long packkey(float f, unsigned idx) {
    unsigned u = __float_as_uint(f);
    u = (u & 0x80000000u) ? ~u : (u | 0x80000000u);
    return ((unsigned long long)u << 32) | (0xFFFFFFFFu - idx);
}
__device__ __forceinline__ float unpackscore(unsigned long long p) {
    unsigned u = (unsigned)(p >> 32);
    unsigned bits = (u & 0x80000000u) ? (u & 0x7FFFFFFFu) : ~u;
    return __uint_as_float(bits);
}
__device__ __forceinline__ unsigned long long umax64(unsigned long long a,
                                                     unsigned long long b) {
    return a > b ? a : b;
}

// ---------------------------------------------------------------------------
// Kernel 1: sim tile GEMM (32 q x 32 f x K=256) on RAW q + fused argmax.
// argmax(q.F^T) == argmax(q_hat.F^T) since 1/||q|| > 0; norm applied at
// score-write time. Grid 256 blocks (qhalf = b>>7, ftile = b&127), 256
// threads, ~78 KB smem -> 2 blocks/SM (16 warps/SM saturates FFMA issue).
// Thread (tx, ty) computes a 2x2 tile; smem reads conflict-free.
// ---------------------------------------------------------------------------
__global__ void __launch_bounds__(256, 2) sim_kernel(const float* __restrict__ q,
                                                     const float* __restrict__ feats) {
    extern __shared__ float sm[];
    float* qs = sm;                          // [256][36]  qs[k*36 + qrow]
    float* fs = sm + TS_FLOATS;              // [256][36]  fs[k*36 + frow]
    unsigned long long* red =
        (unsigned long long*)(sm + 2 * TS_FLOATS);   // [32][16]

    const int tid   = threadIdx.x;
    const int qhalf = blockIdx.x >> 7;
    const int fblk  = blockIdx.x & 127;
    const int f0    = fblk * FPB;
    const int q0    = qhalf * QPB;

    // ---- Stage tiles transposed: 8 coalesced float4 loads per thread each.
    // Thread (r=tid>>3 in [0,32), c=tid&7) loads float4 groups c+8i, i<8
    // (full 64 groups per row). Warp spans 4 rows x 128B -> LDG.128 coalesced.
    {
        const float4* q4 =
            reinterpret_cast<const float4*>(q + (size_t)q0 * DD);
        const float4* f4 =
            reinterpret_cast<const float4*>(feats + (size_t)f0 * DD);
        const int r = tid >> 3;
        const int c = tid & 7;
        float4 v[8], w[8];
        #pragma unroll
        for (int i = 0; i < 8; i++) v[i] = q4[r * 64 + c + 8 * i];
        #pragma unroll
        for (int i = 0; i < 8; i++) w[i] = f4[r * 64 + c + 8 * i];
        #pragma unroll
        for (int i = 0; i < 8; i++) {
            const int k = 4 * (c + 8 * i);
            qs[(k + 0) * TS_STRIDE + r] = v[i].x;
            qs[(k + 1) * TS_STRIDE + r] = v[i].y;
            qs[(k + 2) * TS_STRIDE + r] = v[i].z;
            qs[(k + 3) * TS_STRIDE + r] = v[i].w;
        }
        #pragma unroll
        for (int i = 0; i < 8; i++) {
            const int k = 4 * (c + 8 * i);
            fs[(k + 0) * TS_STRIDE + r] = w[i].x;
            fs[(k + 1) * TS_STRIDE + r] = w[i].y;
            fs[(k + 2) * TS_STRIDE + r] = w[i].z;
            fs[(k + 3) * TS_STRIDE + r] = w[i].w;
        }
    }
    __syncthreads();

    const int tx = tid & 15;                 // q rows 2tx, 2tx+1
    const int ty = tid >> 4;                 // f cols 2ty, 2ty+1
    float acc[2][2] = {{0.f, 0.f}, {0.f, 0.f}};

    #pragma unroll 8
    for (int k = 0; k < DD; k++) {
        float2 a = *reinterpret_cast<const float2*>(&qs[k * TS_STRIDE + 2 * tx]);
        float2 b = *reinterpret_cast<const float2*>(&fs[k * TS_STRIDE + 2 * ty]);
        acc[0][0] = fmaf(a.x, b.x, acc[0][0]);
        acc[0][1] = fmaf(a.x, b.y, acc[0][1]);
        acc[1][0] = fmaf(a.y, b.x, acc[1][0]);
        acc[1][1] = fmaf(a.y, b.y, acc[1][1]);
    }

    // Per-thread max over its 2 features (strict > keeps lowest index on tie)
    #pragma unroll
    for (int i = 0; i < 2; i++) {
        float m = acc[i][0]; int bj = 0;
        if (acc[i][1] > m) { m = acc[i][1]; bj = 1; }
        red[(2 * tx + i) * 16 + ty] = packkey(m, (unsigned)(f0 + 2 * ty + bj));
    }
    __syncthreads();

    // One thread per local query reduces the 16 ty-partials -> private slot.
    if (tid < QPB) {
        unsigned long long p = red[tid * 16];
        #pragma unroll
        for (int j = 1; j < 16; j++) p = umax64(p, red[tid * 16 + j]);
        g_part[(q0 + tid) * FBLOCKS + fblk] = p;
    }
}

// ---------------------------------------------------------------------------
// Kernel 2: per-query final argmax reduce (redundant per block, L2-hot 1 KB)
// + image gather + normalized score write.
// Grid (16 chunks, 64 queries) x 256 threads; each block copies 16 KB.
// (Best-measured config across 5 variants: R6/R11, 8.99 us.) __ldcg skips
// L1 allocation for the zero-reuse image stream.
// ---------------------------------------------------------------------------
__global__ void __launch_bounds__(256, 8) gather_kernel(const float* __restrict__ q,
                                                        const float* __restrict__ images,
                                                        float* __restrict__ out) {
    __shared__ unsigned long long sred[4];
    __shared__ unsigned long long sbest;

    const int qi = blockIdx.y;
    const int t  = threadIdx.x;

    // Reduce 128 per-f-tile partials for this query.
    unsigned long long p = 0ull;
    if (t < FBLOCKS) p = g_part[qi * FBLOCKS + t];
    #pragma unroll
    for (int o = 16; o; o >>= 1)
        p = umax64(p, __shfl_xor_sync(0xffffffffu, p, o));
    if (t < FBLOCKS && (t & 31) == 0) sred[t >> 5] = p;
    __syncthreads();
    if (t == 0) {
        unsigned long long m = sred[0];
        #pragma unroll
        for (int j = 1; j < 4; j++) m = umax64(m, sred[j]);
        sbest = m;
    }
    __syncthreads();

    const unsigned long long best = sbest;
    const unsigned idx = 0xFFFFFFFFu - (unsigned)(best & 0xFFFFFFFFu);

    // Streaming copy of the selected image chunk (loads batched for MLP).
    const float4* src = reinterpret_cast<const float4*>(images + (size_t)idx * IMG)
                        + blockIdx.x * 1024;
    float4* dst = reinterpret_cast<float4*>(out + (size_t)qi * IMG)
                  + blockIdx.x * 1024;
    float4 v[4];
    #pragma unroll
    for (int r = 0; r < 4; r++) v[r] = __ldcg(&src[t + 256 * r]);
    #pragma unroll
    for (int r = 0; r < 4; r++) dst[t + 256 * r] = v[r];

    // Block (0, qi): compute ||q_qi|| with warp 0 and write normalized score.
    if (blockIdx.x == 0 && t < 32) {
        const float4* qr = reinterpret_cast<const float4*>(q + qi * DD);
        float s = 0.f;
        #pragma unroll
        for (int j = 0; j < 2; j++) {
            float4 w = qr[t + 32 * j];
            s += w.x * w.x + w.y * w.y + w.z * w.z + w.w * w.w;
        }
        #pragma unroll
        for (int o = 16; o; o >>= 1) s += __shfl_xor_sync(0xffffffffu, s, o);
        if (t == 0) {
            float norm = fmaxf(sqrtf(s), 1e-12f);
            out[(size_t)NQ * IMG + qi] = unpackscore(best) / norm;
        }
    }
}

// ---------------------------------------------------------------------------
extern "C" void kernel_launch(void* const* d_in, const int* in_sizes, int n_in,
                              void* d_out, int out_size) {
    const float* q      = (const float*)d_in[0];   // (64, 256)
    const float* feats  = (const float*)d_in[1];   // (4096, 256), pre-normalized
    const float* images = (const float*)d_in[2];   // (4096, 1, 256, 256)
    float* out = (float*)d_out;                    // 64*65536 imgs + 64 scores

    cudaFuncSetAttribute(sim_kernel,
                         cudaFuncAttributeMaxDynamicSharedMemorySize, SMEM_BYTES);

    sim_kernel<<<SIMBLOCKS, 256, SMEM_BYTES>>>(q, feats);
    gather_kernel<<<dim3(16, NQ), 256>>>(q, images, out);
}

// round 14
// speedup vs baseline: 1.2393x; 1.2393x over previous
#include <cuda_runtime.h>
#include <math.h>

// Problem constants
#define NQ   64          // queries
#define DD   256         // feature dim
#define NS   4096        // bank size
#define IMG  65536       // C*H*W floats per image
#define FPB  32          // features per sim block
#define FBLOCKS (NS / FPB)   // 128

// smem layout for sim kernel (transposed, padded strides)
#define QS_STRIDE 68     // 64 rows + 4 pad (float4-aligned, conflict-free)
#define FS_STRIDE 36     // 32 rows + 4 pad
#define QS_FLOATS (DD * QS_STRIDE)   // 17408
#define FS_FLOATS (DD * FS_STRIDE)   //  9216
#define RED_SLOTS (NQ * 8)           // per-(query, warp) partials
#define SMEM_BYTES ((QS_FLOATS + FS_FLOATS) * 4 + RED_SLOTS * 8)  // 110592 B

// Per-(query, f-tile) partial argmax results. Every slot is rewritten on
// every replay -> no reset kernel, no atomics, fully deterministic.
__device__ unsigned long long g_part[NQ * FBLOCKS];

__device__ __forceinline__ unsigned long long packkey(float f, unsigned idx) {
    unsigned u = __float_as_uint(f);
    u = (u & 0x80000000u) ? ~u : (u | 0x80000000u);
    return ((unsigned long long)u << 32) | (0xFFFFFFFFu - idx);
}
__device__ __forceinline__ float unpackscore(unsigned long long p) {
    unsigned u = (unsigned)(p >> 32);
    unsigned bits = (u & 0x80000000u) ? (u & 0x7FFFFFFFu) : ~u;
    return __uint_as_float(bits);
}
__device__ __forceinline__ unsigned long long umax64(unsigned long long a,
                                                     unsigned long long b) {
    return a > b ? a : b;
}

// ---------------------------------------------------------------------------
// Kernel 1: sim tile GEMM (64 q x 32 f x K=256) on RAW q + fused argmax.
// argmax(q.F^T) == argmax(q_hat.F^T) since 1/||q|| > 0; norm applied at
// score-write time. 128 blocks x 256 threads.
// Mainloop operand mapping (smem-bandwidth optimized):
//   lane owns q rows 2l,2l+1  -> a = LDS.64  qs[k][2l]   (conflict-free)
//   warp owns features 4w..4w+3 -> b = LDS.128 fs[k][4w] (uniform address =
//   HW broadcast, bandwidth-free). 8 FMA per thread per k.
// Block smem traffic: ~2.2 KB/k-iter (was 6 KB) -> FFMA-issue bound.
// ---------------------------------------------------------------------------
__global__ void __launch_bounds__(256, 1) sim_kernel(const float* __restrict__ q,
                                                     const float* __restrict__ feats) {
    extern __shared__ float sm[];
    float* qs = sm;                          // [256][68]  qs[k*68 + qrow]
    float* fs = sm + QS_FLOATS;              // [256][36]  fs[k*36 + frow]
    unsigned long long* red =
        (unsigned long long*)(sm + QS_FLOATS + FS_FLOATS);   // [64][8]

    const int tid  = threadIdx.x;
    const int lane = tid & 31;
    const int w    = tid >> 5;               // 8 warps
    const int f0   = blockIdx.x * FPB;

    // ---- Stage q transposed: 16 coalesced float4 loads per thread ----
    {
        const float4* q4 = reinterpret_cast<const float4*>(q);
        const int r = tid >> 2;              // 0..63 (warp spans 8 rows x 64B)
        const int c = tid & 3;
        #pragma unroll
        for (int half = 0; half < 2; half++) {
            float4 v[8];
            #pragma unroll
            for (int i = 0; i < 8; i++)
                v[i] = q4[r * 64 + c + 4 * (half * 8 + i)];
            #pragma unroll
            for (int i = 0; i < 8; i++) {
                const int k = 4 * (c + 4 * (half * 8 + i));
                qs[(k + 0) * QS_STRIDE + r] = v[i].x;
                qs[(k + 1) * QS_STRIDE + r] = v[i].y;
                qs[(k + 2) * QS_STRIDE + r] = v[i].z;
                qs[(k + 3) * QS_STRIDE + r] = v[i].w;
            }
        }
    }
    // ---- Stage feature tile transposed: 8 coalesced float4 loads per thread ----
    {
        const float4* f4 =
            reinterpret_cast<const float4*>(feats + (size_t)f0 * DD);
        const int r = tid >> 3;              // 0..31 (warp spans 4 rows x 128B)
        const int c = tid & 7;
        float4 v[8];
        #pragma unroll
        for (int i = 0; i < 8; i++)
            v[i] = f4[r * 64 + c + 8 * i];
        #pragma unroll
        for (int i = 0; i < 8; i++) {
            const int k = 4 * (c + 8 * i);
            fs[(k + 0) * FS_STRIDE + r] = v[i].x;
            fs[(k + 1) * FS_STRIDE + r] = v[i].y;
            fs[(k + 2) * FS_STRIDE + r] = v[i].z;
            fs[(k + 3) * FS_STRIDE + r] = v[i].w;
        }
    }
    __syncthreads();

    float acc[2][4];
    #pragma unroll
    for (int i = 0; i < 2; i++)
        #pragma unroll
        for (int j = 0; j < 4; j++) acc[i][j] = 0.f;

    #pragma unroll 8
    for (int k = 0; k < DD; k++) {
        float2 a = *reinterpret_cast<const float2*>(&qs[k * QS_STRIDE + 2 * lane]);
        float4 b = *reinterpret_cast<const float4*>(&fs[k * FS_STRIDE + 4 * w]);
        float bv[4] = {b.x, b.y, b.z, b.w};
        #pragma unroll
        for (int j = 0; j < 4; j++) {
            acc[0][j] = fmaf(a.x, bv[j], acc[0][j]);
            acc[1][j] = fmaf(a.y, bv[j], acc[1][j]);
        }
    }

    // Per-thread max over its 4 features (strict >, ascending j keeps lowest
    // index on tie); one slot per (query row, warp).
    #pragma unroll
    for (int i = 0; i < 2; i++) {
        float m = acc[i][0]; int bj = 0;
        #pragma unroll
        for (int j = 1; j < 4; j++)
            if (acc[i][j] > m) { m = acc[i][j]; bj = j; }
        red[(2 * lane + i) * 8 + w] = packkey(m, (unsigned)(f0 + 4 * w + bj));
    }
    __syncthreads();

    // One thread per query reduces the 8 warp-partials -> its private slot.
    if (tid < NQ) {
        unsigned long long p = red[tid * 8];
        #pragma unroll
        for (int j = 1; j < 8; j++) p = umax64(p, red[tid * 8 + j]);
        g_part[tid * FBLOCKS + blockIdx.x] = p;
    }
}

// ---------------------------------------------------------------------------
// Kernel 2: per-query final argmax reduce (redundant per block, L2-hot 1 KB)
// + image gather (float4 streaming copy) + normalized score write.
// Grid (16 chunks, 64 queries) x 256 threads; each block copies 16 KB.
// (Exact best-measured config: R6/R11, 8.99 us.)
// ---------------------------------------------------------------------------
__global__ void __launch_bounds__(256, 8) gather_kernel(const float* __restrict__ q,
                                                        const float* __restrict__ images,
                                                        float* __restrict__ out) {
    __shared__ unsigned long long sred[4];
    __shared__ unsigned long long sbest;

    const int qi = blockIdx.y;
    const int t  = threadIdx.x;

    // Reduce 128 per-f-tile partials for this query.
    unsigned long long p = 0ull;
    if (t < FBLOCKS) p = g_part[qi * FBLOCKS + t];
    #pragma unroll
    for (int o = 16; o; o >>= 1)
        p = umax64(p, __shfl_xor_sync(0xffffffffu, p, o));
    if (t < FBLOCKS && (t & 31) == 0) sred[t >> 5] = p;
    __syncthreads();
    if (t == 0) {
        unsigned long long m = sred[0];
        #pragma unroll
        for (int j = 1; j < 4; j++) m = umax64(m, sred[j]);
        sbest = m;
    }
    __syncthreads();

    const unsigned long long best = sbest;
    const unsigned idx = 0xFFFFFFFFu - (unsigned)(best & 0xFFFFFFFFu);

    // Streaming copy of the selected image chunk (loads batched for MLP).
    const float4* src = reinterpret_cast<const float4*>(images + (size_t)idx * IMG)
                        + blockIdx.x * 1024;
    float4* dst = reinterpret_cast<float4*>(out + (size_t)qi * IMG)
                  + blockIdx.x * 1024;
    float4 v[4];
    #pragma unroll
    for (int r = 0; r < 4; r++) v[r] = src[t + 256 * r];
    #pragma unroll
    for (int r = 0; r < 4; r++) dst[t + 256 * r] = v[r];

    // Block (0, qi): compute ||q_qi|| with warp 0 and write normalized score.
    if (blockIdx.x == 0 && t < 32) {
        const float4* qr = reinterpret_cast<const float4*>(q + qi * DD);
        float s = 0.f;
        #pragma unroll
        for (int j = 0; j < 2; j++) {
            float4 w2 = qr[t + 32 * j];
            s += w2.x * w2.x + w2.y * w2.y + w2.z * w2.z + w2.w * w2.w;
        }
        #pragma unroll
        for (int o = 16; o; o >>= 1) s += __shfl_xor_sync(0xffffffffu, s, o);
        if (t == 0) {
            float norm = fmaxf(sqrtf(s), 1e-12f);
            out[(size_t)NQ * IMG + qi] = unpackscore(best) / norm;
        }
    }
}

// ---------------------------------------------------------------------------
extern "C" void kernel_launch(void* const* d_in, const int* in_sizes, int n_in,
                              void* d_out, int out_size) {
    const float* q      = (const float*)d_in[0];   // (64, 256)
    const float* feats  = (const float*)d_in[1];   // (4096, 256), pre-normalized
    const float* images = (const float*)d_in[2];   // (4096, 1, 256, 256)
    float* out = (float*)d_out;                    // 64*65536 imgs + 64 scores

    cudaFuncSetAttribute(sim_kernel,
                         cudaFuncAttributeMaxDynamicSharedMemorySize, SMEM_BYTES);

    sim_kernel<<<FBLOCKS, 256, SMEM_BYTES>>>(q, feats);
    gather_kernel<<<dim3(16, NQ), 256>>>(q, images, out);
}